// round 16
// baseline (speedup 1.0000x reference)
#include <cuda_runtime.h>
#include <cuda_fp16.h>
#include <math.h>
#include <stdint.h>

#define BATCH 2
#define SLEN 4096
#define DMODEL 128
#define NHEAD 4
#define HDIM 32
#define NROW (BATCH*SLEN)   // 8192
#define NHB  (BATCH*NHEAD)  // 8

// Scratch (device globals — no allocation allowed)
__device__ float g_pe[SLEN*DMODEL];
__device__ __align__(16) __half g_qh[NROW*DMODEL], g_ql[NROW*DMODEL];
__device__ __align__(16) __half g_kh[NROW*DMODEL];
__device__ __align__(16) __half g_vh[NROW*DMODEL];
__device__ __align__(16) __half g_oh[NROW*DMODEL], g_ol[NROW*DMODEL];
// fragment-packed weights (hi only): [mat][n-octet(16)][kstep(8)][lane(32)]
__device__ __align__(16) uint2 g_wph[4*4096];
// partial attention outputs (unnormalized fp32) + partial row sums, 2 slots
__device__ __align__(16) float g_po[2L*NHB*SLEN*HDIM];
__device__ float g_pl[2*NHB*SLEN];

// ---------------------------------------------------------------------------
// helpers
// ---------------------------------------------------------------------------
__device__ __forceinline__ uint32_t smem_u32(const void* p) {
    uint32_t a;
    asm("{ .reg .u64 t; cvta.to.shared.u64 t, %1; cvt.u32.u64 %0, t; }" : "=r"(a) : "l"(p));
    return a;
}

// pack two floats -> f16x2 hi (e in low half, o in high) + f16x2 residual
__device__ __forceinline__ void split2h(float e, float o, uint32_t& hi, uint32_t& lo) {
    uint32_t h;
    asm("cvt.rn.f16x2.f32 %0, %1, %2;" : "=r"(h) : "f"(o), "f"(e));
    float2 f = __half22float2(*(__half2*)&h);
    uint32_t l;
    asm("cvt.rn.f16x2.f32 %0, %1, %2;" : "=r"(l) : "f"(o - f.y), "f"(e - f.x));
    hi = h; lo = l;
}
// hi-only pack
__device__ __forceinline__ uint32_t pack2h(float e, float o) {
    uint32_t h;
    asm("cvt.rn.f16x2.f32 %0, %1, %2;" : "=r"(h) : "f"(o), "f"(e));
    return h;
}
// guaranteed single-MUFU exp2
__device__ __forceinline__ float ex2(float x) {
    float r;
    asm("ex2.approx.f32 %0, %1;" : "=f"(r) : "f"(x));
    return r;
}

// D (in-place C) += A * B, m16n8k16 fp16 -> f32
__device__ __forceinline__ void mma_f16(float d[4], const uint32_t a[4], const uint32_t b[2]) {
    asm volatile(
        "mma.sync.aligned.m16n8k16.row.col.f32.f16.f16.f32 "
        "{%0,%1,%2,%3},{%4,%5,%6,%7},{%8,%9},{%0,%1,%2,%3};"
        : "+f"(d[0]), "+f"(d[1]), "+f"(d[2]), "+f"(d[3])
        : "r"(a[0]), "r"(a[1]), "r"(a[2]), "r"(a[3]), "r"(b[0]), "r"(b[1]));
}

__device__ __forceinline__ void ldmx4(uint32_t d[4], uint32_t a) {
    asm volatile("ldmatrix.sync.aligned.m8n8.x4.shared.b16 {%0,%1,%2,%3}, [%4];"
        : "=r"(d[0]), "=r"(d[1]), "=r"(d[2]), "=r"(d[3]) : "r"(a));
}
__device__ __forceinline__ void ldmx4t(uint32_t d[4], uint32_t a) {
    asm volatile("ldmatrix.sync.aligned.m8n8.x4.trans.shared.b16 {%0,%1,%2,%3}, [%4];"
        : "=r"(d[0]), "=r"(d[1]), "=r"(d[2]), "=r"(d[3]) : "r"(a));
}

#define CP16(dst, src) asm volatile("cp.async.cg.shared.global [%0], [%1], 16;" :: "r"(dst), "l"(src) : "memory")
#define CP_COMMIT()    asm volatile("cp.async.commit_group;" ::: "memory")
#define CP_WAIT0()     asm volatile("cp.async.wait_group 0;" ::: "memory")
#define CP_WAIT1()     asm volatile("cp.async.wait_group 1;" ::: "memory")

// ---------------------------------------------------------------------------
// Prep: positional encoding (blocks >= 64) + weight split/pack (blocks < 64)
// ---------------------------------------------------------------------------
__global__ void prep_kernel(const float* __restrict__ wq, const float* __restrict__ wk,
                            const float* __restrict__ wv, const float* __restrict__ wo) {
    int bid = blockIdx.x;
    if (bid < 64) {
        int idx = bid * 256 + threadIdx.x;      // 0..16383
        int mat = idx >> 12, rem = idx & 4095;
        int no = rem >> 8, ks = (rem >> 5) & 7, lane = rem & 31;
        int gg = lane >> 2, uu = lane & 3;
        const float* Ws[4] = {wq, wk, wv, wo};
        const float* W = Ws[mat];
        int n = 8 * no + gg, k0 = 16 * ks + 2 * uu;
        uint32_t h0 = pack2h(W[n*DMODEL + k0],     W[n*DMODEL + k0 + 1]);
        uint32_t h1 = pack2h(W[n*DMODEL + k0 + 8], W[n*DMODEL + k0 + 9]);
        g_wph[idx] = make_uint2(h0, h1);
    } else {
        int idx = (bid - 64) * 256 + threadIdx.x;
        if (idx >= SLEN * (DMODEL/2)) return;
        int s = idx / (DMODEL/2);
        int i = idx % (DMODEL/2);
        float e = (2.0f * (float)i) / (float)DMODEL;
        double divd = exp2((double)e * 13.287712379549449);  // 10000^e
        float fdiv = (float)divd;
        float a = (float)s / fdiv;      // fp32 angle like jax
        float sv, cv;
        sincosf(a, &sv, &cv);           // 2-ulp accurate incl. range reduction
        g_pe[s*DMODEL + 2*i]     = sv;
        g_pe[s*DMODEL + 2*i + 1] = cv;
    }
}

// ---------------------------------------------------------------------------
// QKV projection via HMMA (fp16, 2-term: xh*Wh + xl*Wh). blockIdx.y = matrix.
// Outputs: q scaled by log2e/sqrt(32) hi/lo; k, v hi only.
// ---------------------------------------------------------------------------
__global__ __launch_bounds__(128) void qkv_mma_kernel(
        const int* __restrict__ seq, const float* __restrict__ emb) {
    int tid = threadIdx.x;
    int w = tid >> 5, lane = tid & 31;
    int g = lane >> 2, u = lane & 3;
    int m0 = (blockIdx.x >> 1) * 64 + 16 * w;
    int jbase = (blockIdx.x & 1) * 8;
    int mat = blockIdx.y;

    int ra = m0 + g, rb = ra + 8;
    int tok_a = seq[ra], tok_b = seq[rb];
    int sa = ra & (SLEN - 1), sb = rb & (SLEN - 1);
    const float* Ea = emb + (long)tok_a * DMODEL;
    const float* Eb = emb + (long)tok_b * DMODEL;
    const float* Pa = g_pe + sa * DMODEL;
    const float* Pb = g_pe + sb * DMODEL;

    uint32_t xh[8][4], xl[8][4];
    #pragma unroll
    for (int ks = 0; ks < 8; ks++) {
        int c = 16 * ks + 2 * u;
        float2 e0, p0;
        e0 = *(const float2*)(Ea + c);     p0 = *(const float2*)(Pa + c);
        split2h(e0.x + p0.x, e0.y + p0.y, xh[ks][0], xl[ks][0]);
        e0 = *(const float2*)(Eb + c);     p0 = *(const float2*)(Pb + c);
        split2h(e0.x + p0.x, e0.y + p0.y, xh[ks][1], xl[ks][1]);
        e0 = *(const float2*)(Ea + c + 8); p0 = *(const float2*)(Pa + c + 8);
        split2h(e0.x + p0.x, e0.y + p0.y, xh[ks][2], xl[ks][2]);
        e0 = *(const float2*)(Eb + c + 8); p0 = *(const float2*)(Pb + c + 8);
        split2h(e0.x + p0.x, e0.y + p0.y, xh[ks][3], xl[ks][3]);
    }

    // 1/sqrt(32) * log2(e): folds softmax's exp->exp2 conversion into Q
    const float qscale = 0.17677669529663687f * 1.4426950408889634f;

    const uint2* wph = g_wph + mat * 4096;

    float acc[8][4];
    #pragma unroll
    for (int j = 0; j < 8; j++)
        #pragma unroll
        for (int e = 0; e < 4; e++) acc[j][e] = 0.f;

    #pragma unroll
    for (int ks = 0; ks < 8; ks++) {
        #pragma unroll
        for (int j = 0; j < 8; j++) {
            int no = jbase + j;
            uint2 bhv = wph[(no * 8 + ks) * 32 + lane];
            uint32_t bh[2] = { bhv.x, bhv.y };
            mma_f16(acc[j], xh[ks], bh);
            mma_f16(acc[j], xl[ks], bh);
        }
    }

    #pragma unroll
    for (int j = 0; j < 8; j++) {
        int cbase = (jbase + j) * 8 + 2 * u;
        if (mat == 0) {
            uint32_t h0, l0;
            split2h(acc[j][0] * qscale, acc[j][1] * qscale, h0, l0);
            *(uint32_t*)(g_qh + (long)ra * DMODEL + cbase) = h0;
            *(uint32_t*)(g_ql + (long)ra * DMODEL + cbase) = l0;
            split2h(acc[j][2] * qscale, acc[j][3] * qscale, h0, l0);
            *(uint32_t*)(g_qh + (long)rb * DMODEL + cbase) = h0;
            *(uint32_t*)(g_ql + (long)rb * DMODEL + cbase) = l0;
        } else {
            __half* dst = (mat == 1) ? g_kh : g_vh;
            *(uint32_t*)(dst + (long)ra * DMODEL + cbase) = pack2h(acc[j][0], acc[j][1]);
            *(uint32_t*)(dst + (long)rb * DMODEL + cbase) = pack2h(acc[j][2], acc[j][3]);
        }
    }
}

// ---------------------------------------------------------------------------
// HMMA flash attention v10: fp16, 2-term S / 1-term PV, pair-streamed
// S->softmax->PV per kt (short dependency chains, small live state), MMA row
// sums, complete-tile in-kernel finalize (fp16 O out), balanced pairing,
// 3-stage cp.async pipeline + ldmatrix.x4.
// SMEM per stage: KH,VH each [128 keys][80B stride] = 20KB; 3 stages.
// ---------------------------------------------------------------------------
#define KHOFF 0
#define VHOFF 10240
#define STAGE 20480
#define PSHIFT 5.0f

__device__ __forceinline__ void stage_tile(uint32_t sb,
        const char* kh, const char* vh, int jt, int tid) {
    long base = (long)jt * 128 * 64;   // 128 keys x 64 bytes
    #pragma unroll
    for (int it = 0; it < 2; it++) {
        int gi = tid + it * 256;
        int key = gi >> 2, q4 = gi & 3;
        int d = key * 80 + 16 * q4;
        long s = base + key * 64 + 16 * q4;
        CP16(sb + KHOFF + d, kh + s);
        CP16(sb + VHOFF + d, vh + s);
    }
}

__global__ __launch_bounds__(256, 2) void attn_mma_kernel() {
    extern __shared__ char smem[];
    uint32_t sbase = smem_u32(smem);
    int tid = threadIdx.x;
    int w = tid >> 5, lane = tid & 31;
    int g = lane >> 2, u = lane & 3;

    int x = blockIdx.x;
    int pu = x >> 1, side = x & 1;
    int hb = blockIdx.y;
    long hoff = (long)hb * SLEN * HDIM;

    const char* Kh = (const char*)(g_kh + hoff);
    const char* Vh = (const char*)(g_vh + hoff);
    const __half* Qbh = g_qh + hoff;
    const __half* Qbl = g_ql + hoff;
    float* PO = g_po + ((long)side * NHB + hb) * SLEN * HDIM;
    float* PL = g_pl + ((long)side * NHB + hb) * SLEN;

    // ones-column B fragment for rowsum MMA: V[k][0]=1, others 0
    uint32_t bones[2];
    bones[0] = bones[1] = (g == 0) ? 0x3C003C00u : 0u;

    // balance: side0 = qt=pu full (pu+1) + qt=31-pu [0,15-pu)  -> 16 tiles, 2 segs
    //          side1 = qt=31-pu [15-pu, 32-pu)                 -> 17 tiles, 1 seg
    int qts[2], j0s[2], j1s[2], nseg;
    if (side == 0) {
        qts[0] = pu;      j0s[0] = 0;       j1s[0] = pu + 1;
        qts[1] = 31 - pu; j0s[1] = 0;       j1s[1] = 15 - pu;   // empty at pu=15
        nseg = 2;
    } else {
        qts[0] = 31 - pu; j0s[0] = 15 - pu; j1s[0] = 32 - pu;
        nseg = 1;
    }

    for (int sg = 0; sg < nseg; sg++) {
        int qt = qts[sg], j0 = j0s[sg], j1 = j1s[sg];

        // ---- Q A-fragments (pre-scaled by log2e/sqrt(32), pre-split) ----
        int r0 = qt * 128 + 16 * w + g;
        uint32_t qh[2][4], ql[2][4];
        #pragma unroll
        for (int kt = 0; kt < 2; kt++) {
            int c = 16 * kt + 2 * u;
            qh[kt][0] = *(const uint32_t*)(Qbh + (long)r0 * HDIM + c);
            qh[kt][1] = *(const uint32_t*)(Qbh + (long)(r0 + 8) * HDIM + c);
            qh[kt][2] = *(const uint32_t*)(Qbh + (long)r0 * HDIM + c + 8);
            qh[kt][3] = *(const uint32_t*)(Qbh + (long)(r0 + 8) * HDIM + c + 8);
            ql[kt][0] = *(const uint32_t*)(Qbl + (long)r0 * HDIM + c);
            ql[kt][1] = *(const uint32_t*)(Qbl + (long)(r0 + 8) * HDIM + c);
            ql[kt][2] = *(const uint32_t*)(Qbl + (long)r0 * HDIM + c + 8);
            ql[kt][3] = *(const uint32_t*)(Qbl + (long)(r0 + 8) * HDIM + c + 8);
        }

        float O[4][4], Os[4];
        #pragma unroll
        for (int jo = 0; jo < 4; jo++)
            #pragma unroll
            for (int e = 0; e < 4; e++) O[jo][e] = 0.f;
        #pragma unroll
        for (int e = 0; e < 4; e++) Os[e] = 0.f;

        if (j1 > j0) {
            __syncthreads();   // previous segment done with all buffers
            // ---- pipeline fill: stage j0 (+ j0+1) ----
            stage_tile(sbase, Kh, Vh, j0, tid);
            CP_COMMIT();
            if (j0 + 1 < j1) {
                stage_tile(sbase + STAGE, Kh, Vh, j0 + 1, tid);
                CP_COMMIT();
            }

            int bcur = 0;
            for (int jt = j0; jt < j1; jt++) {
                if (jt + 1 < j1) CP_WAIT1(); else CP_WAIT0();
                __syncthreads();
                // prefetch jt+2 while computing jt
                if (jt + 2 < j1) {
                    int bn = bcur + 2; if (bn >= 3) bn -= 3;
                    stage_tile(sbase + bn * STAGE, Kh, Vh, jt + 2, tid);
                    CP_COMMIT();
                }
                uint32_t sb = sbase + bcur * STAGE;

                bool diag = (jt == qt);
                int rloc0 = 16 * w + g;

                #pragma unroll
                for (int h = 0; h < 2; h++) {
                    if (diag && h == 1 && w < 4) continue;   // fully masked half

                    // ---- pair-streamed: S(2kt,2kt+1) -> softmax -> PV(kt) ----
                    #pragma unroll
                    for (int kt = 0; kt < 4; kt++) {
                        float s[2][4];
                        #pragma unroll
                        for (int jj = 0; jj < 2; jj++) {
                            int j = 2 * kt + jj;
                            uint32_t ka = sb + (64*h + 8*j + (lane & 7)) * 80 + 16 * (lane >> 3);
                            uint32_t bh4[4];
                            ldmx4(bh4, ka + KHOFF);
                            s[jj][0] = 0.f; s[jj][1] = 0.f; s[jj][2] = 0.f; s[jj][3] = 0.f;
                            mma_f16(s[jj], qh[0], &bh4[0]);
                            mma_f16(s[jj], qh[1], &bh4[2]);
                            mma_f16(s[jj], ql[0], &bh4[0]);
                            mma_f16(s[jj], ql[1], &bh4[2]);
                        }

                        if (diag) {
                            #pragma unroll
                            for (int jj = 0; jj < 2; jj++)
                                #pragma unroll
                                for (int e = 0; e < 4; e++) {
                                    float p = ex2(fabsf(s[jj][e]) - PSHIFT);
                                    int col = 64*h + 8*(2*kt+jj) + 2*u + (e & 1);
                                    int row = rloc0 + ((e >= 2) ? 8 : 0);
                                    if (col > row) p = 0.f;
                                    s[jj][e] = p;
                                }
                        } else {
                            #pragma unroll
                            for (int jj = 0; jj < 2; jj++)
                                #pragma unroll
                                for (int e = 0; e < 4; e++)
                                    s[jj][e] = ex2(fabsf(s[jj][e]) - PSHIFT);
                        }

                        uint32_t ah[4];
                        ah[0] = pack2h(s[0][0], s[0][1]);
                        ah[1] = pack2h(s[0][2], s[0][3]);
                        ah[2] = pack2h(s[1][0], s[1][1]);
                        ah[3] = pack2h(s[1][2], s[1][3]);
                        uint32_t rowb = sb + (64*h + 16*kt + (lane & 15)) * 80 + 16 * (lane >> 4);
                        #pragma unroll
                        for (int jop = 0; jop < 2; jop++) {
                            uint32_t vh4[4];
                            ldmx4t(vh4, rowb + VHOFF + 32 * jop);
                            mma_f16(O[2*jop],   ah, &vh4[0]);
                            mma_f16(O[2*jop+1], ah, &vh4[2]);
                        }
                        mma_f16(Os, ah, bones);
                    }
                }
                bcur++; if (bcur == 3) bcur = 0;
            }
        }

        if (side == 0 && sg == 0) {
            // ---- complete tile: finalize in-kernel, store fp16 O hi/lo ----
            float l0 = __shfl_sync(0xffffffffu, Os[0], lane & 28);
            float l1 = __shfl_sync(0xffffffffu, Os[2], lane & 28);
            float inv0 = 1.0f / l0, inv1 = 1.0f / l1;
            __half* Oh = g_oh + hoff;
            __half* Ol = g_ol + hoff;
            #pragma unroll
            for (int jo = 0; jo < 4; jo++) {
                int cb = 8 * jo + 2 * u;
                uint32_t h0, lo0;
                split2h(O[jo][0] * inv0, O[jo][1] * inv0, h0, lo0);
                *(uint32_t*)(Oh + (long)r0 * HDIM + cb) = h0;
                *(uint32_t*)(Ol + (long)r0 * HDIM + cb) = lo0;
                split2h(O[jo][2] * inv1, O[jo][3] * inv1, h0, lo0);
                *(uint32_t*)(Oh + (long)(r0 + 8) * HDIM + cb) = h0;
                *(uint32_t*)(Ol + (long)(r0 + 8) * HDIM + cb) = lo0;
            }
        } else {
            // ---- partial: unnormalized fp32 O + row sums (zeros if empty) ----
            #pragma unroll
            for (int jo = 0; jo < 4; jo++) {
                int cb = 8 * jo + 2 * u;
                *(float2*)(PO + (long)r0 * HDIM + cb)       = make_float2(O[jo][0], O[jo][1]);
                *(float2*)(PO + (long)(r0 + 8) * HDIM + cb) = make_float2(O[jo][2], O[jo][3]);
            }
            if (u == 0) {
                PL[r0]     = Os[0];
                PL[r0 + 8] = Os[2];
            }
        }
    }
}

// ---------------------------------------------------------------------------
// Output projection (256 blocks, n halves, 2-term). Dual path:
//  fast (q-tiles 0-15): A-frags direct fp16 loads from g_oh/g_ol (flat layout
//    == plain-view X);
//  slow (q-tiles 16-31): combine 2 fp32 partial slots + normalize + split.
// Branch is uniform per block: two = ((sa&1023) >= 512).
// ---------------------------------------------------------------------------
__global__ __launch_bounds__(128) void oproj_mma_kernel(float* __restrict__ out) {
    int tid = threadIdx.x;
    int w = tid >> 5, lane = tid & 31;
    int g = lane >> 2, u = lane & 3;
    int m0 = (blockIdx.x >> 1) * 64 + 16 * w;
    int jbase = (blockIdx.x & 1) * 8;

    int ra = m0 + g, rb = ra + 8;
    int ba = ra >> 12, sa = ra & (SLEN - 1);
    int bb = rb >> 12, sb = rb & (SLEN - 1);
    bool two = (sa & 1023) >= 512;   // uniform per block

    uint32_t xh[8][4], xl[8][4];
    if (!two) {
        // ---- fast path: direct fp16 loads ----
        #pragma unroll
        for (int ks = 0; ks < 8; ks++) {
            int c = 16 * ks + 2 * u;
            xh[ks][0] = *(const uint32_t*)(g_oh + (long)ra * DMODEL + c);
            xh[ks][1] = *(const uint32_t*)(g_oh + (long)rb * DMODEL + c);
            xh[ks][2] = *(const uint32_t*)(g_oh + (long)ra * DMODEL + c + 8);
            xh[ks][3] = *(const uint32_t*)(g_oh + (long)rb * DMODEL + c + 8);
            xl[ks][0] = *(const uint32_t*)(g_ol + (long)ra * DMODEL + c);
            xl[ks][1] = *(const uint32_t*)(g_ol + (long)rb * DMODEL + c);
            xl[ks][2] = *(const uint32_t*)(g_ol + (long)ra * DMODEL + c + 8);
            xl[ks][3] = *(const uint32_t*)(g_ol + (long)rb * DMODEL + c + 8);
        }
    } else {
        // ---- slow path: combine fp32 partials, normalize, split ----
        int ha = sa >> 10, hb2 = sb >> 10;
        int pa0 = (sa & 1023) * 4, pb0 = (sb & 1023) * 4;
        const float* PO1 = g_po + (long)NHB * SLEN * HDIM;
        const float* PL1 = g_pl + NHB * SLEN;

        float inva[4], invb[4];
        #pragma unroll
        for (int p = 0; p < 4; p++) {
            long ia = ((long)(ba * 4 + ha)) * SLEN + pa0 + p;
            inva[p] = 1.0f / (g_pl[ia] + PL1[ia]);
            long ib = ((long)(bb * 4 + hb2)) * SLEN + pb0 + p;
            invb[p] = 1.0f / (g_pl[ib] + PL1[ib]);
        }

        #pragma unroll
        for (int ks = 0; ks < 8; ks++) {
            int p = ks >> 1;
            int d0 = (ks & 1) * 16 + 2 * u;
            long base_a = (((long)(ba * 4 + ha)) * SLEN + pa0 + p) * HDIM;
            float2 a0 = *(const float2*)(g_po + base_a + d0);
            float2 a1 = *(const float2*)(g_po + base_a + d0 + 8);
            float2 q0 = *(const float2*)(PO1 + base_a + d0);
            float2 q1 = *(const float2*)(PO1 + base_a + d0 + 8);
            a0.x += q0.x; a0.y += q0.y; a1.x += q1.x; a1.y += q1.y;
            split2h(a0.x * inva[p], a0.y * inva[p], xh[ks][0], xl[ks][0]);
            split2h(a1.x * inva[p], a1.y * inva[p], xh[ks][2], xl[ks][2]);

            long base_b = (((long)(bb * 4 + hb2)) * SLEN + pb0 + p) * HDIM;
            float2 b0 = *(const float2*)(g_po + base_b + d0);
            float2 b1 = *(const float2*)(g_po + base_b + d0 + 8);
            q0 = *(const float2*)(PO1 + base_b + d0);
            q1 = *(const float2*)(PO1 + base_b + d0 + 8);
            b0.x += q0.x; b0.y += q0.y; b1.x += q1.x; b1.y += q1.y;
            split2h(b0.x * invb[p], b0.y * invb[p], xh[ks][1], xl[ks][1]);
            split2h(b1.x * invb[p], b1.y * invb[p], xh[ks][3], xl[ks][3]);
        }
    }

    const uint2* wph = g_wph + 3 * 4096;

    float acc[8][4];
    #pragma unroll
    for (int j = 0; j < 8; j++)
        #pragma unroll
        for (int e = 0; e < 4; e++) acc[j][e] = 0.f;

    #pragma unroll
    for (int ks = 0; ks < 8; ks++) {
        #pragma unroll
        for (int j = 0; j < 8; j++) {
            int no = jbase + j;
            uint2 bhv = wph[(no * 8 + ks) * 32 + lane];
            uint32_t bh[2] = { bhv.x, bhv.y };
            mma_f16(acc[j], xh[ks], bh);
            mma_f16(acc[j], xl[ks], bh);
        }
    }

    #pragma unroll
    for (int j = 0; j < 8; j++) {
        int cbase = (jbase + j) * 8 + 2 * u;
        *(float2*)(out + (long)ra * DMODEL + cbase) = make_float2(acc[j][0], acc[j][1]);
        *(float2*)(out + (long)rb * DMODEL + cbase) = make_float2(acc[j][2], acc[j][3]);
    }
}

extern "C" void kernel_launch(void* const* d_in, const int* in_sizes, int n_in,
                              void* d_out, int out_size) {
    const int*   seq = (const int*)d_in[0];
    const float* emb = (const float*)d_in[1];
    const float* wq  = (const float*)d_in[2];
    const float* wk  = (const float*)d_in[3];
    const float* wv  = (const float*)d_in[4];
    const float* wo  = (const float*)d_in[5];
    float* out = (float*)d_out;

    cudaFuncSetAttribute(attn_mma_kernel,
                         cudaFuncAttributeMaxDynamicSharedMemorySize, 3 * STAGE);

    prep_kernel<<<64 + (SLEN*(DMODEL/2) + 255)/256, 256>>>(wq, wk, wv, wo);
    qkv_mma_kernel<<<dim3(256, 3), 128>>>(seq, emb);
    attn_mma_kernel<<<dim3(32, NHB), 256, 3 * STAGE>>>();
    oproj_mma_kernel<<<256, 128>>>(out);
}

// round 17
// speedup vs baseline: 1.1763x; 1.1763x over previous
#include <cuda_runtime.h>
#include <cuda_fp16.h>
#include <math.h>
#include <stdint.h>

#define BATCH 2
#define SLEN 4096
#define DMODEL 128
#define NHEAD 4
#define HDIM 32
#define NROW (BATCH*SLEN)   // 8192
#define NHB  (BATCH*NHEAD)  // 8

// Scratch (device globals — no allocation allowed)
__device__ float g_pe[SLEN*DMODEL];
__device__ __align__(16) __half g_qh[NROW*DMODEL];
__device__ __align__(16) __half g_kh[NROW*DMODEL];
__device__ __align__(16) __half g_vh[NROW*DMODEL];
// fragment-packed weights (hi only): [mat][n-octet(16)][kstep(8)][lane(32)]
__device__ __align__(16) uint2 g_wph[4*4096];
// partial attention outputs (unnormalized fp32) + partial row sums, 2 slots
__device__ __align__(16) float g_po[2L*NHB*SLEN*HDIM];
__device__ float g_pl[2*NHB*SLEN];

// ---------------------------------------------------------------------------
// helpers
// ---------------------------------------------------------------------------
__device__ __forceinline__ uint32_t smem_u32(const void* p) {
    uint32_t a;
    asm("{ .reg .u64 t; cvta.to.shared.u64 t, %1; cvt.u32.u64 %0, t; }" : "=r"(a) : "l"(p));
    return a;
}

// pack two floats -> f16x2 hi (e in low half, o in high) + f16x2 residual
__device__ __forceinline__ void split2h(float e, float o, uint32_t& hi, uint32_t& lo) {
    uint32_t h;
    asm("cvt.rn.f16x2.f32 %0, %1, %2;" : "=r"(h) : "f"(o), "f"(e));
    float2 f = __half22float2(*(__half2*)&h);
    uint32_t l;
    asm("cvt.rn.f16x2.f32 %0, %1, %2;" : "=r"(l) : "f"(o - f.y), "f"(e - f.x));
    hi = h; lo = l;
}
// hi-only pack
__device__ __forceinline__ uint32_t pack2h(float e, float o) {
    uint32_t h;
    asm("cvt.rn.f16x2.f32 %0, %1, %2;" : "=r"(h) : "f"(o), "f"(e));
    return h;
}
// guaranteed single-MUFU exp2
__device__ __forceinline__ float ex2(float x) {
    float r;
    asm("ex2.approx.f32 %0, %1;" : "=f"(r) : "f"(x));
    return r;
}

// D (in-place C) += A * B, m16n8k16 fp16 -> f32
__device__ __forceinline__ void mma_f16(float d[4], const uint32_t a[4], const uint32_t b[2]) {
    asm volatile(
        "mma.sync.aligned.m16n8k16.row.col.f32.f16.f16.f32 "
        "{%0,%1,%2,%3},{%4,%5,%6,%7},{%8,%9},{%0,%1,%2,%3};"
        : "+f"(d[0]), "+f"(d[1]), "+f"(d[2]), "+f"(d[3])
        : "r"(a[0]), "r"(a[1]), "r"(a[2]), "r"(a[3]), "r"(b[0]), "r"(b[1]));
}

__device__ __forceinline__ void ldmx4(uint32_t d[4], uint32_t a) {
    asm volatile("ldmatrix.sync.aligned.m8n8.x4.shared.b16 {%0,%1,%2,%3}, [%4];"
        : "=r"(d[0]), "=r"(d[1]), "=r"(d[2]), "=r"(d[3]) : "r"(a));
}
__device__ __forceinline__ void ldmx4t(uint32_t d[4], uint32_t a) {
    asm volatile("ldmatrix.sync.aligned.m8n8.x4.trans.shared.b16 {%0,%1,%2,%3}, [%4];"
        : "=r"(d[0]), "=r"(d[1]), "=r"(d[2]), "=r"(d[3]) : "r"(a));
}

#define CP16(dst, src) asm volatile("cp.async.cg.shared.global [%0], [%1], 16;" :: "r"(dst), "l"(src) : "memory")
#define CP_COMMIT()    asm volatile("cp.async.commit_group;" ::: "memory")
#define CP_WAIT0()     asm volatile("cp.async.wait_group 0;" ::: "memory")
#define CP_WAIT1()     asm volatile("cp.async.wait_group 1;" ::: "memory")

// ---------------------------------------------------------------------------
// Prep: positional encoding (blocks >= 64) + weight split/pack (blocks < 64)
// ---------------------------------------------------------------------------
__global__ void prep_kernel(const float* __restrict__ wq, const float* __restrict__ wk,
                            const float* __restrict__ wv, const float* __restrict__ wo) {
    int bid = blockIdx.x;
    if (bid < 64) {
        int idx = bid * 256 + threadIdx.x;      // 0..16383
        int mat = idx >> 12, rem = idx & 4095;
        int no = rem >> 8, ks = (rem >> 5) & 7, lane = rem & 31;
        int gg = lane >> 2, uu = lane & 3;
        const float* Ws[4] = {wq, wk, wv, wo};
        const float* W = Ws[mat];
        int n = 8 * no + gg, k0 = 16 * ks + 2 * uu;
        uint32_t h0 = pack2h(W[n*DMODEL + k0],     W[n*DMODEL + k0 + 1]);
        uint32_t h1 = pack2h(W[n*DMODEL + k0 + 8], W[n*DMODEL + k0 + 9]);
        g_wph[idx] = make_uint2(h0, h1);
    } else {
        int idx = (bid - 64) * 256 + threadIdx.x;
        if (idx >= SLEN * (DMODEL/2)) return;
        int s = idx / (DMODEL/2);
        int i = idx % (DMODEL/2);
        float e = (2.0f * (float)i) / (float)DMODEL;
        double divd = exp2((double)e * 13.287712379549449);  // 10000^e
        float fdiv = (float)divd;
        float a = (float)s / fdiv;      // fp32 angle like jax
        float sv, cv;
        sincosf(a, &sv, &cv);           // 2-ulp accurate incl. range reduction
        g_pe[s*DMODEL + 2*i]     = sv;
        g_pe[s*DMODEL + 2*i + 1] = cv;
    }
}

// ---------------------------------------------------------------------------
// QKV projection via HMMA (fp16, 2-term: xh*Wh + xl*Wh). blockIdx.y = matrix.
// Outputs: q scaled by log2e/sqrt(32); q, k, v all hi only.
// ---------------------------------------------------------------------------
__global__ __launch_bounds__(128) void qkv_mma_kernel(
        const int* __restrict__ seq, const float* __restrict__ emb) {
    int tid = threadIdx.x;
    int w = tid >> 5, lane = tid & 31;
    int g = lane >> 2, u = lane & 3;
    int m0 = (blockIdx.x >> 1) * 64 + 16 * w;
    int jbase = (blockIdx.x & 1) * 8;
    int mat = blockIdx.y;

    int ra = m0 + g, rb = ra + 8;
    int tok_a = seq[ra], tok_b = seq[rb];
    int sa = ra & (SLEN - 1), sb = rb & (SLEN - 1);
    const float* Ea = emb + (long)tok_a * DMODEL;
    const float* Eb = emb + (long)tok_b * DMODEL;
    const float* Pa = g_pe + sa * DMODEL;
    const float* Pb = g_pe + sb * DMODEL;

    uint32_t xh[8][4], xl[8][4];
    #pragma unroll
    for (int ks = 0; ks < 8; ks++) {
        int c = 16 * ks + 2 * u;
        float2 e0, p0;
        e0 = *(const float2*)(Ea + c);     p0 = *(const float2*)(Pa + c);
        split2h(e0.x + p0.x, e0.y + p0.y, xh[ks][0], xl[ks][0]);
        e0 = *(const float2*)(Eb + c);     p0 = *(const float2*)(Pb + c);
        split2h(e0.x + p0.x, e0.y + p0.y, xh[ks][1], xl[ks][1]);
        e0 = *(const float2*)(Ea + c + 8); p0 = *(const float2*)(Pa + c + 8);
        split2h(e0.x + p0.x, e0.y + p0.y, xh[ks][2], xl[ks][2]);
        e0 = *(const float2*)(Eb + c + 8); p0 = *(const float2*)(Pb + c + 8);
        split2h(e0.x + p0.x, e0.y + p0.y, xh[ks][3], xl[ks][3]);
    }

    // 1/sqrt(32) * log2(e): folds softmax's exp->exp2 conversion into Q
    const float qscale = 0.17677669529663687f * 1.4426950408889634f;

    const uint2* wph = g_wph + mat * 4096;

    float acc[8][4];
    #pragma unroll
    for (int j = 0; j < 8; j++)
        #pragma unroll
        for (int e = 0; e < 4; e++) acc[j][e] = 0.f;

    #pragma unroll
    for (int ks = 0; ks < 8; ks++) {
        #pragma unroll
        for (int j = 0; j < 8; j++) {
            int no = jbase + j;
            uint2 bhv = wph[(no * 8 + ks) * 32 + lane];
            uint32_t bh[2] = { bhv.x, bhv.y };
            mma_f16(acc[j], xh[ks], bh);
            mma_f16(acc[j], xl[ks], bh);
        }
    }

    float sc = (mat == 0) ? (0.17677669529663687f * 1.4426950408889634f) : 1.0f;
    __half* dst = (mat == 0) ? g_qh : ((mat == 1) ? g_kh : g_vh);
    #pragma unroll
    for (int j = 0; j < 8; j++) {
        int cbase = (jbase + j) * 8 + 2 * u;
        *(uint32_t*)(dst + (long)ra * DMODEL + cbase) = pack2h(acc[j][0] * sc, acc[j][1] * sc);
        *(uint32_t*)(dst + (long)rb * DMODEL + cbase) = pack2h(acc[j][2] * sc, acc[j][3] * sc);
    }
}

// ---------------------------------------------------------------------------
// HMMA flash attention v11: fp16 hi-only Q/K/V (1-term S, 1-term PV),
// exponent-shifted MUFU exp2, diag/non-diag softmax, MMA row sums,
// balanced pairing, 3-stage cp.async pipeline + ldmatrix.x4.
// SMEM per stage: KH,VH each [128 keys][80B stride] = 20KB; 3 stages.
// ---------------------------------------------------------------------------
#define KHOFF 0
#define VHOFF 10240
#define STAGE 20480
#define PSHIFT 5.0f

__device__ __forceinline__ void stage_tile(uint32_t sb,
        const char* kh, const char* vh, int jt, int tid) {
    long base = (long)jt * 128 * 64;   // 128 keys x 64 bytes
    #pragma unroll
    for (int it = 0; it < 2; it++) {
        int gi = tid + it * 256;
        int key = gi >> 2, q4 = gi & 3;
        int d = key * 80 + 16 * q4;
        long s = base + key * 64 + 16 * q4;
        CP16(sb + KHOFF + d, kh + s);
        CP16(sb + VHOFF + d, vh + s);
    }
}

__global__ __launch_bounds__(256, 2) void attn_mma_kernel() {
    extern __shared__ char smem[];
    uint32_t sbase = smem_u32(smem);
    int tid = threadIdx.x;
    int w = tid >> 5, lane = tid & 31;
    int g = lane >> 2, u = lane & 3;

    int x = blockIdx.x;
    int pu = x >> 1, side = x & 1;
    int hb = blockIdx.y;
    long hoff = (long)hb * SLEN * HDIM;

    const char* Kh = (const char*)(g_kh + hoff);
    const char* Vh = (const char*)(g_vh + hoff);
    const __half* Qbh = g_qh + hoff;
    float* PO = g_po + ((long)side * NHB + hb) * SLEN * HDIM;
    float* PL = g_pl + ((long)side * NHB + hb) * SLEN;

    // ones-column B fragment for rowsum MMA: V[k][0]=1, others 0
    uint32_t bones[2];
    bones[0] = bones[1] = (g == 0) ? 0x3C003C00u : 0u;

    // balance: side0 = qt=pu full (pu+1) + qt=31-pu [0,15-pu)  -> 16 tiles, 2 segs
    //          side1 = qt=31-pu [15-pu, 32-pu)                 -> 17 tiles, 1 seg
    int qts[2], j0s[2], j1s[2], nseg;
    if (side == 0) {
        qts[0] = pu;      j0s[0] = 0;       j1s[0] = pu + 1;
        qts[1] = 31 - pu; j0s[1] = 0;       j1s[1] = 15 - pu;   // empty at pu=15
        nseg = 2;
    } else {
        qts[0] = 31 - pu; j0s[0] = 15 - pu; j1s[0] = 32 - pu;
        nseg = 1;
    }

    for (int sg = 0; sg < nseg; sg++) {
        int qt = qts[sg], j0 = j0s[sg], j1 = j1s[sg];

        // ---- Q A-fragments (pre-scaled by log2e/sqrt(32), hi only) ----
        int r0 = qt * 128 + 16 * w + g;
        uint32_t qh[2][4];
        #pragma unroll
        for (int kt = 0; kt < 2; kt++) {
            int c = 16 * kt + 2 * u;
            qh[kt][0] = *(const uint32_t*)(Qbh + (long)r0 * HDIM + c);
            qh[kt][1] = *(const uint32_t*)(Qbh + (long)(r0 + 8) * HDIM + c);
            qh[kt][2] = *(const uint32_t*)(Qbh + (long)r0 * HDIM + c + 8);
            qh[kt][3] = *(const uint32_t*)(Qbh + (long)(r0 + 8) * HDIM + c + 8);
        }

        float O[4][4], Os[4];
        #pragma unroll
        for (int jo = 0; jo < 4; jo++)
            #pragma unroll
            for (int e = 0; e < 4; e++) O[jo][e] = 0.f;
        #pragma unroll
        for (int e = 0; e < 4; e++) Os[e] = 0.f;

        if (j1 > j0) {
            __syncthreads();   // previous segment done with all buffers
            // ---- pipeline fill: stage j0 (+ j0+1) ----
            stage_tile(sbase, Kh, Vh, j0, tid);
            CP_COMMIT();
            if (j0 + 1 < j1) {
                stage_tile(sbase + STAGE, Kh, Vh, j0 + 1, tid);
                CP_COMMIT();
            }

            int bcur = 0;
            for (int jt = j0; jt < j1; jt++) {
                if (jt + 1 < j1) CP_WAIT1(); else CP_WAIT0();
                __syncthreads();
                // prefetch jt+2 while computing jt
                if (jt + 2 < j1) {
                    int bn = bcur + 2; if (bn >= 3) bn -= 3;
                    stage_tile(sbase + bn * STAGE, Kh, Vh, jt + 2, tid);
                    CP_COMMIT();
                }
                uint32_t sb = sbase + bcur * STAGE;

                bool diag = (jt == qt);
                int rloc0 = 16 * w + g;

                #pragma unroll
                for (int h = 0; h < 2; h++) {
                    if (diag && h == 1 && w < 4) continue;   // fully masked half

                    // ---- S = qh K^T over 64 keys (ldmatrix.x4) ----
                    float s[8][4];
                    #pragma unroll
                    for (int j = 0; j < 8; j++) {
                        uint32_t ka = sb + (64*h + 8*j + (lane & 7)) * 80 + 16 * (lane >> 3);
                        uint32_t bh4[4];
                        ldmx4(bh4, ka + KHOFF);
                        s[j][0] = 0.f; s[j][1] = 0.f; s[j][2] = 0.f; s[j][3] = 0.f;
                        mma_f16(s[j], qh[0], &bh4[0]);
                        mma_f16(s[j], qh[1], &bh4[2]);
                    }

                    // ---- softmax: p' = 2^(|s'| - PSHIFT); shift cancels ----
                    if (diag) {
                        #pragma unroll
                        for (int j = 0; j < 8; j++) {
                            #pragma unroll
                            for (int e = 0; e < 4; e++) {
                                float p = ex2(fabsf(s[j][e]) - PSHIFT);
                                int col = 64*h + 8*j + 2*u + (e & 1);
                                int row = rloc0 + ((e >= 2) ? 8 : 0);
                                if (col > row) p = 0.f;
                                s[j][e] = p;
                            }
                        }
                    } else {
                        #pragma unroll
                        for (int j = 0; j < 8; j++)
                            #pragma unroll
                            for (int e = 0; e < 4; e++)
                                s[j][e] = ex2(fabsf(s[j][e]) - PSHIFT);
                    }

                    // ---- O += P V; Os += P 1 (rowsum via constant-B MMA) ----
                    #pragma unroll
                    for (int kt = 0; kt < 4; kt++) {
                        uint32_t ah[4];
                        ah[0] = pack2h(s[2*kt][0],   s[2*kt][1]);
                        ah[1] = pack2h(s[2*kt][2],   s[2*kt][3]);
                        ah[2] = pack2h(s[2*kt+1][0], s[2*kt+1][1]);
                        ah[3] = pack2h(s[2*kt+1][2], s[2*kt+1][3]);
                        uint32_t rowb = sb + (64*h + 16*kt + (lane & 15)) * 80 + 16 * (lane >> 4);
                        #pragma unroll
                        for (int jop = 0; jop < 2; jop++) {
                            uint32_t vh4[4];
                            ldmx4t(vh4, rowb + VHOFF + 32 * jop);
                            mma_f16(O[2*jop],   ah, &vh4[0]);
                            mma_f16(O[2*jop+1], ah, &vh4[2]);
                        }
                        mma_f16(Os, ah, bones);
                    }
                }
                bcur++; if (bcur == 3) bcur = 0;
            }
        }

        // ---- store unnormalized partial O + partial row sums (zeros if empty) --
        #pragma unroll
        for (int jo = 0; jo < 4; jo++) {
            int cb = 8 * jo + 2 * u;
            *(float2*)(PO + (long)r0 * HDIM + cb)       = make_float2(O[jo][0], O[jo][1]);
            *(float2*)(PO + (long)(r0 + 8) * HDIM + cb) = make_float2(O[jo][2], O[jo][3]);
        }
        if (u == 0) {
            PL[r0]     = Os[0];   // C[g][0]   = rowsum(row r0)
            PL[r0 + 8] = Os[2];   // C[g+8][0] = rowsum(row r0+8)
        }
    }
}

// ---------------------------------------------------------------------------
// Output projection with fused attention epilogue (256 blocks, n halves,
// 2-term: xh*Wh + xl*Wh).
// Plain-view mapping: X row ra (within-batch row sa) belongs ENTIRELY to head
// h' = sa>>10; column c is seq position (sa&1023)*4 + (c>>5), dim c&31.
// For kstep ks: pos offset p = ks>>1, dim base = (ks&1)*16 + 2u (+8).
// ---------------------------------------------------------------------------
__global__ __launch_bounds__(128) void oproj_mma_kernel(float* __restrict__ out) {
    int tid = threadIdx.x;
    int w = tid >> 5, lane = tid & 31;
    int g = lane >> 2, u = lane & 3;
    int m0 = (blockIdx.x >> 1) * 64 + 16 * w;
    int jbase = (blockIdx.x & 1) * 8;

    int ra = m0 + g, rb = ra + 8;
    int ba = ra >> 12, sa = ra & (SLEN - 1);
    int bb = rb >> 12, sb = rb & (SLEN - 1);
    int ha = sa >> 10, hb2 = sb >> 10;                 // head index (fixed per row)
    int pa0 = (sa & 1023) * 4, pb0 = (sb & 1023) * 4;  // base seq position
    bool two_a = (sa & 1023) >= 512;
    bool two_b = (sb & 1023) >= 512;
    const float* PO1 = g_po + (long)NHB * SLEN * HDIM;
    const float* PL1 = g_pl + NHB * SLEN;

    // normalizers: one per pos offset (0..3)
    float inva[4], invb[4];
    #pragma unroll
    for (int p = 0; p < 4; p++) {
        long ia = ((long)(ba * 4 + ha)) * SLEN + pa0 + p;
        float la = g_pl[ia] + (two_a ? PL1[ia] : 0.f);
        inva[p] = 1.0f / la;
        long ib = ((long)(bb * 4 + hb2)) * SLEN + pb0 + p;
        float lb = g_pl[ib] + (two_b ? PL1[ib] : 0.f);
        invb[p] = 1.0f / lb;
    }

    uint32_t xh[8][4], xl[8][4];
    #pragma unroll
    for (int ks = 0; ks < 8; ks++) {
        int p = ks >> 1;
        int d0 = (ks & 1) * 16 + 2 * u;
        long base_a = (((long)(ba * 4 + ha)) * SLEN + pa0 + p) * HDIM;
        float2 a0 = *(const float2*)(g_po + base_a + d0);
        float2 a1 = *(const float2*)(g_po + base_a + d0 + 8);
        if (two_a) {
            float2 q0 = *(const float2*)(PO1 + base_a + d0);
            float2 q1 = *(const float2*)(PO1 + base_a + d0 + 8);
            a0.x += q0.x; a0.y += q0.y; a1.x += q1.x; a1.y += q1.y;
        }
        split2h(a0.x * inva[p], a0.y * inva[p], xh[ks][0], xl[ks][0]);
        split2h(a1.x * inva[p], a1.y * inva[p], xh[ks][2], xl[ks][2]);

        long base_b = (((long)(bb * 4 + hb2)) * SLEN + pb0 + p) * HDIM;
        float2 b0 = *(const float2*)(g_po + base_b + d0);
        float2 b1 = *(const float2*)(g_po + base_b + d0 + 8);
        if (two_b) {
            float2 q0 = *(const float2*)(PO1 + base_b + d0);
            float2 q1 = *(const float2*)(PO1 + base_b + d0 + 8);
            b0.x += q0.x; b0.y += q0.y; b1.x += q1.x; b1.y += q1.y;
        }
        split2h(b0.x * invb[p], b0.y * invb[p], xh[ks][1], xl[ks][1]);
        split2h(b1.x * invb[p], b1.y * invb[p], xh[ks][3], xl[ks][3]);
    }

    const uint2* wph = g_wph + 3 * 4096;

    float acc[8][4];
    #pragma unroll
    for (int j = 0; j < 8; j++)
        #pragma unroll
        for (int e = 0; e < 4; e++) acc[j][e] = 0.f;

    #pragma unroll
    for (int ks = 0; ks < 8; ks++) {
        #pragma unroll
        for (int j = 0; j < 8; j++) {
            int no = jbase + j;
            uint2 bhv = wph[(no * 8 + ks) * 32 + lane];
            uint32_t bh[2] = { bhv.x, bhv.y };
            mma_f16(acc[j], xh[ks], bh);
            mma_f16(acc[j], xl[ks], bh);
        }
    }

    #pragma unroll
    for (int j = 0; j < 8; j++) {
        int cbase = (jbase + j) * 8 + 2 * u;
        *(float2*)(out + (long)ra * DMODEL + cbase) = make_float2(acc[j][0], acc[j][1]);
        *(float2*)(out + (long)rb * DMODEL + cbase) = make_float2(acc[j][2], acc[j][3]);
    }
}

extern "C" void kernel_launch(void* const* d_in, const int* in_sizes, int n_in,
                              void* d_out, int out_size) {
    const int*   seq = (const int*)d_in[0];
    const float* emb = (const float*)d_in[1];
    const float* wq  = (const float*)d_in[2];
    const float* wk  = (const float*)d_in[3];
    const float* wv  = (const float*)d_in[4];
    const float* wo  = (const float*)d_in[5];
    float* out = (float*)d_out;

    cudaFuncSetAttribute(attn_mma_kernel,
                         cudaFuncAttributeMaxDynamicSharedMemorySize, 3 * STAGE);

    prep_kernel<<<64 + (SLEN*(DMODEL/2) + 255)/256, 256>>>(wq, wk, wv, wo);
    qkv_mma_kernel<<<dim3(256, 3), 128>>>(seq, emb);
    attn_mma_kernel<<<dim3(32, NHB), 256, 3 * STAGE>>>();
    oproj_mma_kernel<<<256, 128>>>(out);
}